// round 3
// baseline (speedup 1.0000x reference)
#include <cuda_runtime.h>
#include <stdint.h>

#define FDIM 64
#define TDIM 192
#define MAX_ATOMS 50000

// Scratch for the per-atom MLP output t = Dense(silu(Dense(s)))  [N, 192]
__device__ float g_t[(size_t)MAX_ATOMS * TDIM];

// ---------------------------------------------------------------------------
// Vectorized global reduction: 16B atomic add (4 floats in one L2 op).
// ---------------------------------------------------------------------------
__device__ __forceinline__ void red_add_v4(float* addr, float4 v) {
    asm volatile("red.global.add.v4.f32 [%0], {%1, %2, %3, %4};"
                 :: "l"(addr), "f"(v.x), "f"(v.y), "f"(v.z), "f"(v.w)
                 : "memory");
}

// ---------------------------------------------------------------------------
// Kernel A: initialize output.  q = s, mu = v.   (out = [q | mu] contiguous)
// ---------------------------------------------------------------------------
__global__ void __launch_bounds__(256) init_out_kernel(
        const float4* __restrict__ s,   // n_atoms*16 float4
        const float4* __restrict__ v,   // n_atoms*48 float4
        float4* __restrict__ out,       // n_atoms*64 float4
        int nq4, int ntot4) {
    int k = blockIdx.x * blockDim.x + threadIdx.x;
    if (k >= ntot4) return;
    out[k] = (k < nq4) ? s[k] : v[k - nq4];
}

// ---------------------------------------------------------------------------
// Kernel B: per-atom MLP.  t = silu(s @ W1 + b1) @ W2 + b2
// Block = 256 threads, processes 128 atoms.  Weights live in smem (64KB),
// s/h tile (32KB) double-used.  8x4 register tiles per thread.
// ---------------------------------------------------------------------------
__global__ void __launch_bounds__(256) mlp_kernel(
        const float* __restrict__ s,
        const float* __restrict__ W1, const float* __restrict__ b1,
        const float* __restrict__ W2, const float* __restrict__ b2,
        int n_atoms) {
    extern __shared__ float sm[];
    float* sW1 = sm;             // 64*64   = 4096
    float* sW2 = sW1 + 4096;     // 64*192  = 12288
    float* sB1 = sW2 + 12288;    // 64
    float* sB2 = sB1 + 64;       // 192
    float* sS  = sB2 + 192;      // 128*64  = 8192  (s tile, then h tile)

    const int tid = threadIdx.x;
    for (int k = tid; k < 4096;  k += 256) sW1[k] = W1[k];
    for (int k = tid; k < 12288; k += 256) sW2[k] = W2[k];
    if (tid < 64)  sB1[tid] = b1[tid];
    if (tid < 192) sB2[tid] = b2[tid];

    const int a0 = blockIdx.x * 128;
    for (int k = tid; k < 128 * 64; k += 256) {
        int a = k >> 6;
        sS[k] = (a0 + a < n_atoms) ? s[(size_t)(a0 + a) * 64 + (k & 63)] : 0.0f;
    }
    __syncthreads();

    const int tx = tid & 15;   // output-column group (4 cols)
    const int ty = tid >> 4;   // row lane: rows ty + 16*i

    // ---- phase 1: h = silu(s @ W1 + b1) ----
    float acc[8][4];
    #pragma unroll
    for (int i = 0; i < 8; i++)
        acc[i][0] = acc[i][1] = acc[i][2] = acc[i][3] = 0.0f;

    #pragma unroll 8
    for (int k = 0; k < 64; k++) {
        float4 wv = *(const float4*)(sW1 + k * 64 + tx * 4);
        #pragma unroll
        for (int i = 0; i < 8; i++) {
            float sv = sS[(ty + 16 * i) * 64 + k];
            acc[i][0] = fmaf(sv, wv.x, acc[i][0]);
            acc[i][1] = fmaf(sv, wv.y, acc[i][1]);
            acc[i][2] = fmaf(sv, wv.z, acc[i][2]);
            acc[i][3] = fmaf(sv, wv.w, acc[i][3]);
        }
    }
    float4 bb = *(const float4*)(sB1 + tx * 4);
    __syncthreads();   // all reads of sS done before overwriting with h

    #pragma unroll
    for (int i = 0; i < 8; i++) {
        int r = ty + 16 * i;
        float4 h;
        h.x = acc[i][0] + bb.x;
        h.y = acc[i][1] + bb.y;
        h.z = acc[i][2] + bb.z;
        h.w = acc[i][3] + bb.w;
        h.x = h.x / (1.0f + __expf(-h.x));
        h.y = h.y / (1.0f + __expf(-h.y));
        h.z = h.z / (1.0f + __expf(-h.z));
        h.w = h.w / (1.0f + __expf(-h.w));
        *(float4*)(sS + r * 64 + tx * 4) = h;
    }
    __syncthreads();

    // ---- phase 2: t = h @ W2 + b2  (192 outputs in 3 passes of 64) ----
    #pragma unroll 1
    for (int pass = 0; pass < 3; pass++) {
        float a2[8][4];
        #pragma unroll
        for (int i = 0; i < 8; i++)
            a2[i][0] = a2[i][1] = a2[i][2] = a2[i][3] = 0.0f;

        #pragma unroll 8
        for (int k = 0; k < 64; k++) {
            float4 wv = *(const float4*)(sW2 + k * 192 + pass * 64 + tx * 4);
            #pragma unroll
            for (int i = 0; i < 8; i++) {
                float hv = sS[(ty + 16 * i) * 64 + k];
                a2[i][0] = fmaf(hv, wv.x, a2[i][0]);
                a2[i][1] = fmaf(hv, wv.y, a2[i][1]);
                a2[i][2] = fmaf(hv, wv.z, a2[i][2]);
                a2[i][3] = fmaf(hv, wv.w, a2[i][3]);
            }
        }
        float4 b2v = *(const float4*)(sB2 + pass * 64 + tx * 4);
        #pragma unroll
        for (int i = 0; i < 8; i++) {
            int r = ty + 16 * i;
            if (a0 + r < n_atoms) {
                float4 o;
                o.x = a2[i][0] + b2v.x;
                o.y = a2[i][1] + b2v.y;
                o.z = a2[i][2] + b2v.z;
                o.w = a2[i][3] + b2v.w;
                *(float4*)(g_t + (size_t)(a0 + r) * 192 + pass * 64 + tx * 4) = o;
            }
        }
    }
}

// ---------------------------------------------------------------------------
// Kernel C: per-pair message + scatter.
// 16 threads per pair; thread owns float4 lane f4 (4 consecutive f of F=64).
//   w = W_ij * t[j]  ->  ds1|ds2|ds3
//   q[i]  += ds1                      (red.v4)
//   mu[i][d] += ds2*dir[d] + ds3*v[j][d]   d=0..2   (3x red.v4)
// W_ij / dir streamed with evict-first (.cs) so L2 keeps t/v/q/mu resident.
// NOTE: pairlist is int32 (JAX x64-disabled downcasts jnp.int64 -> int32).
// ---------------------------------------------------------------------------
__global__ void __launch_bounds__(256) pair_kernel(
        const float4* __restrict__ W,      // [P * 48] float4
        const float* __restrict__ dir,     // [P * 3]
        const int* __restrict__ pl,        // [2 * P] int32
        const float4* __restrict__ vvec,   // [N * 48] float4
        float* __restrict__ q,             // [N * 64]
        float* __restrict__ mu,            // [N * 192]
        int n_pairs) {
    long long gid = (long long)blockIdx.x * blockDim.x + threadIdx.x;
    int p = (int)(gid >> 4);
    if (p >= n_pairs) return;
    int f4 = (int)(gid & 15);

    int ai = __ldg(pl + p);
    int aj = __ldg(pl + n_pairs + p);

    const float4* Wp = W + (long long)p * 48;
    float4 w1 = __ldcs(Wp + f4);
    float4 w2 = __ldcs(Wp + 16 + f4);
    float4 w3 = __ldcs(Wp + 32 + f4);

    const float4* tj = (const float4*)g_t + (long long)aj * 48;
    float4 t1 = __ldg(tj + f4);
    float4 t2 = __ldg(tj + 16 + f4);
    float4 t3 = __ldg(tj + 32 + f4);

    float4 ds1 = make_float4(w1.x * t1.x, w1.y * t1.y, w1.z * t1.z, w1.w * t1.w);
    float4 ds2 = make_float4(w2.x * t2.x, w2.y * t2.y, w2.z * t2.z, w2.w * t2.w);
    float4 ds3 = make_float4(w3.x * t3.x, w3.y * t3.y, w3.z * t3.z, w3.w * t3.w);

    red_add_v4(q + (long long)ai * 64 + f4 * 4, ds1);

    float d0 = __ldcs(dir + (long long)p * 3 + 0);
    float d1 = __ldcs(dir + (long long)p * 3 + 1);
    float d2 = __ldcs(dir + (long long)p * 3 + 2);

    const float4* vj = vvec + (long long)aj * 48;
    float* mub = mu + (long long)ai * 192 + f4 * 4;

    {
        float4 vv = __ldg(vj + f4);
        float4 r = make_float4(fmaf(ds2.x, d0, ds3.x * vv.x),
                               fmaf(ds2.y, d0, ds3.y * vv.y),
                               fmaf(ds2.z, d0, ds3.z * vv.z),
                               fmaf(ds2.w, d0, ds3.w * vv.w));
        red_add_v4(mub, r);
    }
    {
        float4 vv = __ldg(vj + 16 + f4);
        float4 r = make_float4(fmaf(ds2.x, d1, ds3.x * vv.x),
                               fmaf(ds2.y, d1, ds3.y * vv.y),
                               fmaf(ds2.z, d1, ds3.z * vv.z),
                               fmaf(ds2.w, d1, ds3.w * vv.w));
        red_add_v4(mub + 64, r);
    }
    {
        float4 vv = __ldg(vj + 32 + f4);
        float4 r = make_float4(fmaf(ds2.x, d2, ds3.x * vv.x),
                               fmaf(ds2.y, d2, ds3.y * vv.y),
                               fmaf(ds2.z, d2, ds3.z * vv.z),
                               fmaf(ds2.w, d2, ds3.w * vv.w));
        red_add_v4(mub + 128, r);
    }
}

// ---------------------------------------------------------------------------
extern "C" void kernel_launch(void* const* d_in, const int* in_sizes, int n_in,
                              void* d_out, int out_size) {
    const float* s       = (const float*)d_in[0];   // [N,1,64]
    const float* v       = (const float*)d_in[1];   // [N,3,64]
    const float* W       = (const float*)d_in[2];   // [P,192]
    const float* dir     = (const float*)d_in[3];   // [P,3]
    const int*   pl      = (const int*)d_in[4];     // [2,P] int32
    const float* W1      = (const float*)d_in[5];
    const float* b1      = (const float*)d_in[6];
    const float* W2      = (const float*)d_in[7];
    const float* b2      = (const float*)d_in[8];

    int n_atoms = in_sizes[0] / FDIM;
    int n_pairs = in_sizes[3] / 3;

    float* q  = (float*)d_out;
    float* mu = q + (long long)n_atoms * FDIM;

    // A: init output (q = s, mu = v)
    int nq4   = n_atoms * 16;
    int ntot4 = n_atoms * 64;
    init_out_kernel<<<(ntot4 + 255) / 256, 256>>>(
        (const float4*)s, (const float4*)v, (float4*)d_out, nq4, ntot4);

    // B: per-atom MLP -> g_t
    const size_t MLP_SMEM = (size_t)(4096 + 12288 + 64 + 192 + 128 * 64) * sizeof(float);
    cudaFuncSetAttribute(mlp_kernel, cudaFuncAttributeMaxDynamicSharedMemorySize,
                         (int)MLP_SMEM);
    mlp_kernel<<<(n_atoms + 127) / 128, 256, MLP_SMEM>>>(s, W1, b1, W2, b2, n_atoms);

    // C: per-pair message + scatter
    long long total = (long long)n_pairs * 16;
    int blocks = (int)((total + 255) / 256);
    pair_kernel<<<blocks, 256>>>((const float4*)W, dir, pl, (const float4*)v,
                                 q, mu, n_pairs);
}